// round 6
// baseline (speedup 1.0000x reference)
#include <cuda_runtime.h>
#include <cuda_bf16.h>
#include <cstdint>

// ===========================================================================
// Child-Sum Tree-LSTM, B=8, L=8192, D=768 — warp-level HMMA (mma.sync bf16).
//
// Per level (M parents, 2M children):
//   hsum_split : h_sum = h_l + h_r (fp32) -> bf16 hi/lo pair
//   GEMM-B     : Uh[2M,768]   = h_child @ U_f^T          (fp32 out)
//   GEMM-A     : gates[M,3072] = h_sum @ Wfused^T  + fused LSTM epilogue
//                  f_l = sig(wfx + Uh[2m]); f_r = sig(wfx + Uh[2m+1])
//                  c = sig(i)tanh(u) + f_l c_l + f_r c_r; h = sig(o)tanh(c)
//
// fp32 emulated as bf16 x3: K=2304 sections A=[hi|lo|hi], B=[hi|hi|lo].
// GEMM-A weight columns are PERMUTED so that the 4 gates of feature j land
// in one thread's C-fragment registers:
//   n = 16*s + 8*tp + 2*q + e  <->  j = 4*s + q,  gate g = 2*tp + e
// so the LSTM epilogue runs entirely from accumulator registers.
// ===========================================================================

#define D_      768
#define KTOT    2304
#define NA      3072
#define NB      768
#define MAXP    32768
#define MAXC    65536

typedef __nv_bfloat16 bf16;

// ---- scratch (static device globals; allocation is forbidden) ----
__device__ bf16  g_leaf_hi[(size_t)MAXC * D_];
__device__ bf16  g_leaf_lo[(size_t)MAXC * D_];
__device__ bf16  g_hXhi[(size_t)MAXP * D_], g_hXlo[(size_t)MAXP * D_];
__device__ bf16  g_hYhi[(size_t)MAXP * D_], g_hYlo[(size_t)MAXP * D_];
__device__ float g_cX[(size_t)MAXP * D_],  g_cY[(size_t)MAXP * D_];
__device__ bf16  g_shi[(size_t)MAXP * D_], g_slo[(size_t)MAXP * D_];
__device__ float g_Uh[(size_t)MAXC * D_];
__device__ bf16  g_WbA[(size_t)NA * KTOT];   // [n][k] K-contiguous (permuted n)
__device__ bf16  g_WbB[(size_t)NB * KTOT];   // [n][k] identity n

__device__ __forceinline__ float sigm(float x) { return 1.0f / (1.0f + __expf(-x)); }

__device__ __forceinline__ void mma_bf16(float& d0, float& d1, float& d2, float& d3,
                                         uint32_t a0, uint32_t a1, uint32_t a2, uint32_t a3,
                                         uint32_t b0, uint32_t b1) {
    asm volatile(
        "mma.sync.aligned.m16n8k16.row.col.f32.bf16.bf16.f32 "
        "{%0,%1,%2,%3}, {%4,%5,%6,%7}, {%8,%9}, {%0,%1,%2,%3};"
        : "+f"(d0), "+f"(d1), "+f"(d2), "+f"(d3)
        : "r"(a0), "r"(a1), "r"(a2), "r"(a3), "r"(b0), "r"(b1));
}

// ---------------------------------------------------------------------------
// Weight prep (bf16 x3 split along K: sections [hi|hi|lo]).
// prep_wA applies the gate permutation described above.
// ---------------------------------------------------------------------------
__global__ void prep_wA(const float* __restrict__ W_iou, const float* __restrict__ U_iou,
                        const float* __restrict__ W_f) {
    size_t idx = (size_t)blockIdx.x * blockDim.x + threadIdx.x;
    if (idx >= (size_t)NA * KTOT) return;
    int n = (int)(idx / KTOT), k = (int)(idx % KTOT);
    int s = n >> 4, w = n & 15;
    int tp = w >> 3, q = (w >> 1) & 3, e = w & 1;
    int j = 4 * s + q, g = 2 * tp + e;
    int sec = k / D_, kp = k - sec * D_;
    float wv;
    if (g < 3) {
        int r = g * D_ + j;
        wv = 0.5f * W_iou[(size_t)r * D_ + kp] + U_iou[(size_t)r * D_ + kp];
    } else {
        wv = 0.5f * W_f[(size_t)j * D_ + kp];
    }
    bf16 hi = __float2bfloat16_rn(wv);
    g_WbA[idx] = (sec < 2) ? hi : __float2bfloat16_rn(wv - __bfloat162float(hi));
}
__global__ void prep_wB(const float* __restrict__ U_f) {
    size_t idx = (size_t)blockIdx.x * blockDim.x + threadIdx.x;
    if (idx >= (size_t)NB * KTOT) return;
    int n = (int)(idx / KTOT), k = (int)(idx % KTOT);
    int sec = k / D_, kp = k - sec * D_;
    float wv = U_f[(size_t)n * D_ + kp];
    bf16 hi = __float2bfloat16_rn(wv);
    g_WbB[idx] = (sec < 2) ? hi : __float2bfloat16_rn(wv - __bfloat162float(hi));
}
__global__ void leaf_split(const float* __restrict__ leaf) {
    size_t idx = (size_t)blockIdx.x * blockDim.x + threadIdx.x;
    if (idx >= (size_t)MAXC * D_) return;
    float v = leaf[idx];
    bf16 hi = __float2bfloat16_rn(v);
    g_leaf_hi[idx] = hi;
    g_leaf_lo[idx] = __float2bfloat16_rn(v - __bfloat162float(hi));
}
__global__ void hsum_split(const float* __restrict__ leaf,
                           const bf16* __restrict__ chhi, const bf16* __restrict__ chlo,
                           int use_leaf, int M) {
    size_t idx = (size_t)blockIdx.x * blockDim.x + threadIdx.x;
    if (idx >= (size_t)M * D_) return;
    int m = (int)(idx / D_), k = (int)(idx % D_);
    size_t il = (size_t)(2 * m) * D_ + k, ir = il + D_;
    float hl, hr;
    if (use_leaf) { hl = leaf[il]; hr = leaf[ir]; }
    else {
        hl = __bfloat162float(chhi[il]) + __bfloat162float(chlo[il]);
        hr = __bfloat162float(chhi[ir]) + __bfloat162float(chlo[ir]);
    }
    float s = hl + hr;
    bf16 hi = __float2bfloat16_rn(s);
    g_shi[idx] = hi;
    g_slo[idx] = __float2bfloat16_rn(s - __bfloat162float(hi));
}

// ---------------------------------------------------------------------------
// HMMA GEMM: block 256m x 128n, 8 warps (4m x 2n), warp tile 64x64.
// K in 72 slabs of 32, double-buffered smem (pad 40 -> conflict-free).
// mode 0: store raw fp32 -> Uh.   mode 1: LSTM epilogue.   mode 2: + final.
// ---------------------------------------------------------------------------
#define BM 256
#define BN 128
#define BK 32
#define KP 40                     // padded row length (bf16 elems)
#define NSLAB (KTOT / BK)         // 72
#define ABYTES (BM * KP * 2)      // 20480
#define BBYTES (BN * KP * 2)      // 10240
#define DYNSM  (2 * (ABYTES + BBYTES))   // 61440

__global__ __launch_bounds__(256, 1)
void mma_kernel(const bf16* __restrict__ Ahi, const bf16* __restrict__ Alo,
                const bf16* __restrict__ Wb, int Mrows, int mode,
                float* __restrict__ Uh,
                const float* __restrict__ cprev, int czero,
                float* __restrict__ cnext,
                bf16* __restrict__ hhi, bf16* __restrict__ hlo,
                float* __restrict__ dout,
                const float* __restrict__ b_iou, const float* __restrict__ b_f) {
    extern __shared__ __align__(16) char smem[];
    bf16* As[2] = { (bf16*)smem, (bf16*)(smem + ABYTES) };
    bf16* Bs[2] = { (bf16*)(smem + 2 * ABYTES), (bf16*)(smem + 2 * ABYTES + BBYTES) };

    const int tid = threadIdx.x;
    const int lane = tid & 31, wid = tid >> 5;
    const int wm = wid >> 1, wn = wid & 1;      // 4x2 warp grid
    const int m0 = blockIdx.y * BM;
    const int n0 = blockIdx.x * BN;
    const int gq = lane >> 2, tq = lane & 3;    // groupID, thread-in-group

    float acc[4][8][4];
#pragma unroll
    for (int i = 0; i < 4; ++i)
#pragma unroll
        for (int n = 0; n < 8; ++n)
#pragma unroll
            for (int c = 0; c < 4; ++c) acc[i][n][c] = 0.0f;

    // staging registers
    uint4 ar[4], br[2];
    const int brow = tid >> 1, bhalf = tid & 1;

    auto stage = [&](int s) {
        const int kb = s * BK;
        const int sec = kb / D_;
        const bf16* Asrc = (sec == 1) ? Alo : Ahi;
        const int kk = kb - sec * D_;
        const int m = m0 + tid;
#pragma unroll
        for (int kc = 0; kc < 4; ++kc)
            ar[kc] = (m < Mrows)
                ? *(const uint4*)(Asrc + (size_t)m * D_ + kk + kc * 8)
                : make_uint4(0u, 0u, 0u, 0u);
#pragma unroll
        for (int kc = 0; kc < 2; ++kc)
            br[kc] = *(const uint4*)(Wb + (size_t)(n0 + brow) * KTOT + kb
                                     + (bhalf * 2 + kc) * 8);
    };

    stage(0);
    for (int s = 0; s < NSLAB; ++s) {
        const int b = s & 1;
        // commit staged slab
#pragma unroll
        for (int kc = 0; kc < 4; ++kc)
            *(uint4*)(As[b] + (size_t)tid * KP + kc * 8) = ar[kc];
#pragma unroll
        for (int kc = 0; kc < 2; ++kc)
            *(uint4*)(Bs[b] + (size_t)brow * KP + (bhalf * 2 + kc) * 8) = br[kc];
        __syncthreads();

        if (s + 1 < NSLAB) stage(s + 1);   // LDG overlaps compute

        const bf16* Ab = As[b];
        const bf16* Bb = Bs[b];
#pragma unroll
        for (int kh = 0; kh < 2; ++kh) {
            const int kf = kh * 16 + tq * 2;
            uint32_t afr[4][4];
#pragma unroll
            for (int mt = 0; mt < 4; ++mt) {
                const int r = wm * 64 + mt * 16 + gq;
                const bf16* p = Ab + (size_t)r * KP + kf;
                afr[mt][0] = *(const uint32_t*)(p);
                afr[mt][1] = *(const uint32_t*)(p + 8 * KP);
                afr[mt][2] = *(const uint32_t*)(p + 8);
                afr[mt][3] = *(const uint32_t*)(p + 8 * KP + 8);
            }
            uint32_t bfr[8][2];
#pragma unroll
            for (int nt = 0; nt < 8; ++nt) {
                const int n = wn * 64 + nt * 8 + gq;
                const bf16* p = Bb + (size_t)n * KP + kf;
                bfr[nt][0] = *(const uint32_t*)(p);
                bfr[nt][1] = *(const uint32_t*)(p + 8);
            }
#pragma unroll
            for (int mt = 0; mt < 4; ++mt)
#pragma unroll
                for (int nt = 0; nt < 8; ++nt)
                    mma_bf16(acc[mt][nt][0], acc[mt][nt][1],
                             acc[mt][nt][2], acc[mt][nt][3],
                             afr[mt][0], afr[mt][1], afr[mt][2], afr[mt][3],
                             bfr[nt][0], bfr[nt][1]);
        }
        __syncthreads();
    }

    // ------------------- epilogue (all from registers) -------------------
    if (mode == 0) {
        // identity n: Uh[gm][n] stores; c0,c1 = row gq; c2,c3 = row gq+8
#pragma unroll
        for (int mt = 0; mt < 4; ++mt) {
#pragma unroll
            for (int rh = 0; rh < 2; ++rh) {
                const int gm = m0 + wm * 64 + mt * 16 + gq + rh * 8;
                if (gm >= Mrows) continue;
#pragma unroll
                for (int nt = 0; nt < 8; ++nt) {
                    const int n = n0 + wn * 64 + nt * 8 + tq * 2;
                    float2 v = make_float2(acc[mt][nt][rh * 2 + 0],
                                           acc[mt][nt][rh * 2 + 1]);
                    *(float2*)(Uh + (size_t)gm * D_ + n) = v;
                }
            }
        }
        return;
    }

    const int jb = (n0 + wn * 64) >> 2;   // j base for this warp
#pragma unroll
    for (int ntp = 0; ntp < 4; ++ntp) {
        const int j = jb + ntp * 4 + tq;
        const float bi = b_iou[j], bo = b_iou[D_ + j],
                    bu = b_iou[2 * D_ + j], bfv = b_f[j];
#pragma unroll
        for (int mt = 0; mt < 4; ++mt) {
#pragma unroll
            for (int rh = 0; rh < 2; ++rh) {
                const int gm = m0 + wm * 64 + mt * 16 + gq + rh * 8;
                if (gm >= Mrows) continue;
                float iv  = acc[mt][2 * ntp + 0][rh * 2 + 0] + bi;
                float ov  = acc[mt][2 * ntp + 0][rh * 2 + 1] + bo;
                float uv  = acc[mt][2 * ntp + 1][rh * 2 + 0] + bu;
                float wfx = acc[mt][2 * ntp + 1][rh * 2 + 1] + bfv;
                float uhl = Uh[(size_t)(2 * gm) * D_ + j];
                float uhr = Uh[(size_t)(2 * gm + 1) * D_ + j];
                float fl = sigm(wfx + uhl), fr = sigm(wfx + uhr);
                float cl = 0.f, cr = 0.f;
                if (!czero) {
                    cl = cprev[(size_t)(2 * gm) * D_ + j];
                    cr = cprev[(size_t)(2 * gm + 1) * D_ + j];
                }
                float cn = sigm(iv) * tanhf(uv) + fl * cl + fr * cr;
                float hn = sigm(ov) * tanhf(cn);
                if (mode == 2) {
                    dout[(size_t)gm * D_ + j] = hn;
                    dout[8 * D_ + (size_t)gm * D_ + j] = cn;
                } else {
                    bf16 hi = __float2bfloat16_rn(hn);
                    hhi[(size_t)gm * D_ + j] = hi;
                    hlo[(size_t)gm * D_ + j] =
                        __float2bfloat16_rn(hn - __bfloat162float(hi));
                    cnext[(size_t)gm * D_ + j] = cn;
                }
            }
        }
    }
}

// ---------------------------------------------------------------------------
extern "C" void kernel_launch(void* const* d_in, const int* in_sizes, int n_in,
                              void* d_out, int out_size) {
    const float* leaf  = (const float*)d_in[0];
    const float* W_iou = (const float*)d_in[1];
    const float* b_iou = (const float*)d_in[2];
    const float* U_iou = (const float*)d_in[3];
    const float* W_f   = (const float*)d_in[4];
    const float* b_f   = (const float*)d_in[5];
    const float* U_f   = (const float*)d_in[6];
    float* out = (float*)d_out;

    cudaFuncSetAttribute(mma_kernel,
                         cudaFuncAttributeMaxDynamicSharedMemorySize, DYNSM);

    { size_t t = (size_t)NA * KTOT;  prep_wA<<<(unsigned)((t + 255) / 256), 256>>>(W_iou, U_iou, W_f); }
    { size_t t = (size_t)NB * KTOT;  prep_wB<<<(unsigned)((t + 255) / 256), 256>>>(U_f); }
    { size_t t = (size_t)MAXC * D_;  leaf_split<<<(unsigned)((t + 255) / 256), 256>>>(leaf); }

    bf16 *leafHi, *leafLo, *hXhi, *hXlo, *hYhi, *hYlo, *shi, *slo, *WbA, *WbB;
    float *cX, *cY, *Uh;
    cudaGetSymbolAddress((void**)&leafHi, g_leaf_hi);
    cudaGetSymbolAddress((void**)&leafLo, g_leaf_lo);
    cudaGetSymbolAddress((void**)&hXhi, g_hXhi);
    cudaGetSymbolAddress((void**)&hXlo, g_hXlo);
    cudaGetSymbolAddress((void**)&hYhi, g_hYhi);
    cudaGetSymbolAddress((void**)&hYlo, g_hYlo);
    cudaGetSymbolAddress((void**)&cX, g_cX);
    cudaGetSymbolAddress((void**)&cY, g_cY);
    cudaGetSymbolAddress((void**)&shi, g_shi);
    cudaGetSymbolAddress((void**)&slo, g_slo);
    cudaGetSymbolAddress((void**)&Uh, g_Uh);
    cudaGetSymbolAddress((void**)&WbA, g_WbA);
    cudaGetSymbolAddress((void**)&WbB, g_WbB);

    int Mp = MAXP;
    for (int lvl = 0; lvl < 13; ++lvl) {
        const bf16* chi = (lvl == 0) ? leafHi : ((lvl & 1) ? hXhi : hYhi);
        const bf16* clo = (lvl == 0) ? leafLo : ((lvl & 1) ? hXlo : hYlo);
        const float* cpv = (lvl & 1) ? cX : cY;
        bf16* dhi = (lvl & 1) ? hYhi : hXhi;
        bf16* dlo = (lvl & 1) ? hYlo : hXlo;
        float* cnx = (lvl & 1) ? cY : cX;

        { size_t t = (size_t)Mp * D_;
          hsum_split<<<(unsigned)((t + 255) / 256), 256>>>(leaf, chi, clo, lvl == 0, Mp); }

        // GEMM-B: Uh over 2*Mp children rows
        {
            dim3 g(NB / BN, (unsigned)((2 * Mp + BM - 1) / BM));
            mma_kernel<<<g, 256, DYNSM>>>(chi, clo, WbB, 2 * Mp, 0,
                                          Uh, nullptr, 1, nullptr, nullptr,
                                          nullptr, nullptr, b_iou, b_f);
        }
        // GEMM-A: gates over Mp parent rows + fused LSTM epilogue
        {
            dim3 g(NA / BN, (unsigned)((Mp + BM - 1) / BM));
            mma_kernel<<<g, 256, DYNSM>>>(shi, slo, WbA, Mp, (lvl == 12) ? 2 : 1,
                                          Uh, cpv, lvl == 0 ? 1 : 0, cnx,
                                          dhi, dlo, out, b_iou, b_f);
        }
        Mp >>= 1;
    }
}

// round 7
// speedup vs baseline: 1.5266x; 1.5266x over previous
#include <cuda_runtime.h>
#include <cuda_bf16.h>
#include <cstdint>

// ===========================================================================
// Child-Sum Tree-LSTM, B=8, L=8192, D=768 — warp-level HMMA (mma.sync bf16),
// cp.async 3-stage pipelined mainloop, 512 threads, warp tile 64x32.
//
// Per level (M parents, 2M children):
//   hsum_split : h_sum = h_l + h_r (fp32) -> bf16 hi/lo pair
//   GEMM-B     : Uh[2M,768]   = h_child @ U_f^T          (fp32 out)
//   GEMM-A     : gates[M,3072] = h_sum @ Wfused^T  + fused LSTM epilogue
//                  f_l = sig(wfx + Uh[2m]); f_r = sig(wfx + Uh[2m+1])
//                  c = sig(i)tanh(u) + f_l c_l + f_r c_r; h = sig(o)tanh(c)
//
// fp32 emulated as bf16 x3: K=2304 sections A=[hi|lo|hi], B=[hi|hi|lo].
// GEMM-A weight columns are PERMUTED so the 4 gates of feature j land in one
// thread's C-fragment registers:
//   n = 16*s + 8*tp + 2*q + e  <->  j = 4*s + q,  gate g = 2*tp + e.
// (Numerics/mappings identical to the R6-validated kernel, rel_err 1.5e-5.)
// ===========================================================================

#define D_      768
#define KTOT    2304
#define NA      3072
#define NB      768
#define MAXP    32768
#define MAXC    65536

typedef __nv_bfloat16 bf16;

// ---- scratch (static device globals; allocation is forbidden) ----
__device__ bf16  g_leaf_hi[(size_t)MAXC * D_];
__device__ bf16  g_leaf_lo[(size_t)MAXC * D_];
__device__ bf16  g_hXhi[(size_t)MAXP * D_], g_hXlo[(size_t)MAXP * D_];
__device__ bf16  g_hYhi[(size_t)MAXP * D_], g_hYlo[(size_t)MAXP * D_];
__device__ float g_cX[(size_t)MAXP * D_],  g_cY[(size_t)MAXP * D_];
__device__ bf16  g_shi[(size_t)MAXP * D_], g_slo[(size_t)MAXP * D_];
__device__ float g_Uh[(size_t)MAXC * D_];
__device__ bf16  g_WbA[(size_t)NA * KTOT];   // [n][k] K-contiguous (permuted n)
__device__ bf16  g_WbB[(size_t)NB * KTOT];   // [n][k] identity n

__device__ __forceinline__ float sigm(float x) { return 1.0f / (1.0f + __expf(-x)); }

__device__ __forceinline__ void mma_bf16(float& d0, float& d1, float& d2, float& d3,
                                         uint32_t a0, uint32_t a1, uint32_t a2, uint32_t a3,
                                         uint32_t b0, uint32_t b1) {
    asm volatile(
        "mma.sync.aligned.m16n8k16.row.col.f32.bf16.bf16.f32 "
        "{%0,%1,%2,%3}, {%4,%5,%6,%7}, {%8,%9}, {%0,%1,%2,%3};"
        : "+f"(d0), "+f"(d1), "+f"(d2), "+f"(d3)
        : "r"(a0), "r"(a1), "r"(a2), "r"(a3), "r"(b0), "r"(b1));
}

__device__ __forceinline__ void cp16(uint32_t dst_smem, const void* src, int srcsize) {
    asm volatile("cp.async.cg.shared.global [%0], [%1], 16, %2;"
                 :: "r"(dst_smem), "l"(src), "r"(srcsize));
}

// ---------------------------------------------------------------------------
// Weight prep (bf16 x3 split along K: sections [hi|hi|lo]).
// ---------------------------------------------------------------------------
__global__ void prep_wA(const float* __restrict__ W_iou, const float* __restrict__ U_iou,
                        const float* __restrict__ W_f) {
    size_t idx = (size_t)blockIdx.x * blockDim.x + threadIdx.x;
    if (idx >= (size_t)NA * KTOT) return;
    int n = (int)(idx / KTOT), k = (int)(idx % KTOT);
    int s = n >> 4, w = n & 15;
    int tp = w >> 3, q = (w >> 1) & 3, e = w & 1;
    int j = 4 * s + q, g = 2 * tp + e;
    int sec = k / D_, kp = k - sec * D_;
    float wv;
    if (g < 3) {
        int r = g * D_ + j;
        wv = 0.5f * W_iou[(size_t)r * D_ + kp] + U_iou[(size_t)r * D_ + kp];
    } else {
        wv = 0.5f * W_f[(size_t)j * D_ + kp];
    }
    bf16 hi = __float2bfloat16_rn(wv);
    g_WbA[idx] = (sec < 2) ? hi : __float2bfloat16_rn(wv - __bfloat162float(hi));
}
__global__ void prep_wB(const float* __restrict__ U_f) {
    size_t idx = (size_t)blockIdx.x * blockDim.x + threadIdx.x;
    if (idx >= (size_t)NB * KTOT) return;
    int n = (int)(idx / KTOT), k = (int)(idx % KTOT);
    int sec = k / D_, kp = k - sec * D_;
    float wv = U_f[(size_t)n * D_ + kp];
    bf16 hi = __float2bfloat16_rn(wv);
    g_WbB[idx] = (sec < 2) ? hi : __float2bfloat16_rn(wv - __bfloat162float(hi));
}
__global__ void leaf_split(const float* __restrict__ leaf) {
    size_t idx = (size_t)blockIdx.x * blockDim.x + threadIdx.x;
    if (idx >= (size_t)MAXC * D_) return;
    float v = leaf[idx];
    bf16 hi = __float2bfloat16_rn(v);
    g_leaf_hi[idx] = hi;
    g_leaf_lo[idx] = __float2bfloat16_rn(v - __bfloat162float(hi));
}
__global__ void hsum_split(const float* __restrict__ leaf,
                           const bf16* __restrict__ chhi, const bf16* __restrict__ chlo,
                           int use_leaf, int M) {
    size_t idx = (size_t)blockIdx.x * blockDim.x + threadIdx.x;
    if (idx >= (size_t)M * D_) return;
    int m = (int)(idx / D_), k = (int)(idx % D_);
    size_t il = (size_t)(2 * m) * D_ + k, ir = il + D_;
    float hl, hr;
    if (use_leaf) { hl = leaf[il]; hr = leaf[ir]; }
    else {
        hl = __bfloat162float(chhi[il]) + __bfloat162float(chlo[il]);
        hr = __bfloat162float(chhi[ir]) + __bfloat162float(chlo[ir]);
    }
    float s = hl + hr;
    bf16 hi = __float2bfloat16_rn(s);
    g_shi[idx] = hi;
    g_slo[idx] = __float2bfloat16_rn(s - __bfloat162float(hi));
}

// ---------------------------------------------------------------------------
// HMMA GEMM: block 256m x 128n, 16 warps (4m x 4n), warp tile 64x32.
// K in 72 slabs of 32, cp.async 3-stage pipeline (prefetch depth 2).
// mode 0: store raw fp32 -> Uh.   mode 1: LSTM epilogue.   mode 2: + final.
// ---------------------------------------------------------------------------
#define BM 256
#define BN 128
#define BK 32
#define KP 40                     // padded row length (bf16 elems) -> 80B rows
#define NSLAB (KTOT / BK)         // 72
#define ABYTES (BM * KP * 2)      // 20480
#define BBYTES (BN * KP * 2)      // 10240
#define STAGEB (ABYTES + BBYTES)  // 30720
#define NSTAGE 3
#define DYNSM  (NSTAGE * STAGEB)  // 92160

__global__ __launch_bounds__(512, 1)
void mma_kernel(const bf16* __restrict__ Ahi, const bf16* __restrict__ Alo,
                const bf16* __restrict__ Wb, int Mrows, int mode,
                float* __restrict__ Uh,
                const float* __restrict__ cprev, int czero,
                float* __restrict__ cnext,
                bf16* __restrict__ hhi, bf16* __restrict__ hlo,
                float* __restrict__ dout,
                const float* __restrict__ b_iou, const float* __restrict__ b_f) {
    extern __shared__ __align__(16) char smem[];
    const uint32_t smem_base = (uint32_t)__cvta_generic_to_shared(smem);

    const int tid = threadIdx.x;
    const int lane = tid & 31, wid = tid >> 5;
    const int wm = wid >> 2, wn = wid & 3;      // 4x4 warp grid
    const int m0 = blockIdx.y * BM;
    const int n0 = blockIdx.x * BN;
    const int gq = lane >> 2, tq = lane & 3;    // groupID, thread-in-group

    float acc[4][4][4];
#pragma unroll
    for (int i = 0; i < 4; ++i)
#pragma unroll
        for (int n = 0; n < 4; ++n)
#pragma unroll
            for (int c = 0; c < 4; ++c) acc[i][n][c] = 0.0f;

    // ---- cp.async slab issue: A 16KB (2 chunks/thread), B 8KB (1 chunk) ----
    auto issue = [&](int s) {
        const int kb = s * BK;
        const int sec = kb / D_;
        const bf16* Asrc = (sec == 1) ? Alo : Ahi;
        const int kk = kb - sec * D_;
        const uint32_t sA = smem_base + (uint32_t)(s % NSTAGE) * STAGEB;
        const uint32_t sB = sA + ABYTES;
#pragma unroll
        for (int i = 0; i < 2; ++i) {
            int id = tid + i * 512, row = id >> 2, kc = id & 3;
            int m = m0 + row;
            cp16(sA + row * 80 + kc * 16,
                 Asrc + (size_t)m * D_ + kk + kc * 8,
                 (m < Mrows) ? 16 : 0);
        }
        {
            int row = tid >> 2, kc = tid & 3;
            cp16(sB + row * 80 + kc * 16,
                 Wb + (size_t)(n0 + row) * KTOT + kb + kc * 8, 16);
        }
        asm volatile("cp.async.commit_group;" ::: "memory");
    };

    issue(0); issue(1); issue(2);

    for (int s = 0; s < NSLAB; ++s) {
        asm volatile("cp.async.wait_group 2;" ::: "memory");
        __syncthreads();

        const bf16* Ab = (const bf16*)(smem + (size_t)(s % NSTAGE) * STAGEB);
        const bf16* Bb = (const bf16*)(smem + (size_t)(s % NSTAGE) * STAGEB + ABYTES);
#pragma unroll
        for (int kh = 0; kh < 2; ++kh) {
            const int kf = kh * 16 + tq * 2;
            uint32_t afr[4][4];
#pragma unroll
            for (int mt = 0; mt < 4; ++mt) {
                const int r = wm * 64 + mt * 16 + gq;
                const bf16* p = Ab + (size_t)r * KP + kf;
                afr[mt][0] = *(const uint32_t*)(p);
                afr[mt][1] = *(const uint32_t*)(p + 8 * KP);
                afr[mt][2] = *(const uint32_t*)(p + 8);
                afr[mt][3] = *(const uint32_t*)(p + 8 * KP + 8);
            }
            uint32_t bfr[4][2];
#pragma unroll
            for (int nt = 0; nt < 4; ++nt) {
                const int n = wn * 32 + nt * 8 + gq;
                const bf16* p = Bb + (size_t)n * KP + kf;
                bfr[nt][0] = *(const uint32_t*)(p);
                bfr[nt][1] = *(const uint32_t*)(p + 8);
            }
#pragma unroll
            for (int mt = 0; mt < 4; ++mt)
#pragma unroll
                for (int nt = 0; nt < 4; ++nt)
                    mma_bf16(acc[mt][nt][0], acc[mt][nt][1],
                             acc[mt][nt][2], acc[mt][nt][3],
                             afr[mt][0], afr[mt][1], afr[mt][2], afr[mt][3],
                             bfr[nt][0], bfr[nt][1]);
        }
        __syncthreads();
        if (s + 3 < NSLAB) issue(s + 3);
    }

    // ------------------- epilogue (all from registers) -------------------
    if (mode == 0) {
#pragma unroll
        for (int mt = 0; mt < 4; ++mt) {
#pragma unroll
            for (int rh = 0; rh < 2; ++rh) {
                const int gm = m0 + wm * 64 + mt * 16 + gq + rh * 8;
                if (gm >= Mrows) continue;
#pragma unroll
                for (int nt = 0; nt < 4; ++nt) {
                    const int n = n0 + wn * 32 + nt * 8 + tq * 2;
                    float2 v = make_float2(acc[mt][nt][rh * 2 + 0],
                                           acc[mt][nt][rh * 2 + 1]);
                    *(float2*)(Uh + (size_t)gm * D_ + n) = v;
                }
            }
        }
        return;
    }

    const int jb = (n0 + wn * 32) >> 2;   // j base for this warp
#pragma unroll
    for (int ntp = 0; ntp < 2; ++ntp) {
        const int j = jb + ntp * 4 + tq;
        const float bi = b_iou[j], bo = b_iou[D_ + j],
                    bu = b_iou[2 * D_ + j], bfv = b_f[j];
#pragma unroll
        for (int mt = 0; mt < 4; ++mt) {
#pragma unroll
            for (int rh = 0; rh < 2; ++rh) {
                const int gm = m0 + wm * 64 + mt * 16 + gq + rh * 8;
                if (gm >= Mrows) continue;
                float iv  = acc[mt][2 * ntp + 0][rh * 2 + 0] + bi;
                float ov  = acc[mt][2 * ntp + 0][rh * 2 + 1] + bo;
                float uv  = acc[mt][2 * ntp + 1][rh * 2 + 0] + bu;
                float wfx = acc[mt][2 * ntp + 1][rh * 2 + 1] + bfv;
                float uhl = Uh[(size_t)(2 * gm) * D_ + j];
                float uhr = Uh[(size_t)(2 * gm + 1) * D_ + j];
                float fl = sigm(wfx + uhl), fr = sigm(wfx + uhr);
                float cl = 0.f, cr = 0.f;
                if (!czero) {
                    cl = cprev[(size_t)(2 * gm) * D_ + j];
                    cr = cprev[(size_t)(2 * gm + 1) * D_ + j];
                }
                float cn = sigm(iv) * tanhf(uv) + fl * cl + fr * cr;
                float hn = sigm(ov) * tanhf(cn);
                if (mode == 2) {
                    dout[(size_t)gm * D_ + j] = hn;
                    dout[8 * D_ + (size_t)gm * D_ + j] = cn;
                } else {
                    bf16 hi = __float2bfloat16_rn(hn);
                    hhi[(size_t)gm * D_ + j] = hi;
                    hlo[(size_t)gm * D_ + j] =
                        __float2bfloat16_rn(hn - __bfloat162float(hi));
                    cnext[(size_t)gm * D_ + j] = cn;
                }
            }
        }
    }
}

// ---------------------------------------------------------------------------
extern "C" void kernel_launch(void* const* d_in, const int* in_sizes, int n_in,
                              void* d_out, int out_size) {
    const float* leaf  = (const float*)d_in[0];
    const float* W_iou = (const float*)d_in[1];
    const float* b_iou = (const float*)d_in[2];
    const float* U_iou = (const float*)d_in[3];
    const float* W_f   = (const float*)d_in[4];
    const float* b_f   = (const float*)d_in[5];
    const float* U_f   = (const float*)d_in[6];
    float* out = (float*)d_out;

    cudaFuncSetAttribute(mma_kernel,
                         cudaFuncAttributeMaxDynamicSharedMemorySize, DYNSM);

    { size_t t = (size_t)NA * KTOT;  prep_wA<<<(unsigned)((t + 255) / 256), 256>>>(W_iou, U_iou, W_f); }
    { size_t t = (size_t)NB * KTOT;  prep_wB<<<(unsigned)((t + 255) / 256), 256>>>(U_f); }
    { size_t t = (size_t)MAXC * D_;  leaf_split<<<(unsigned)((t + 255) / 256), 256>>>(leaf); }

    bf16 *leafHi, *leafLo, *hXhi, *hXlo, *hYhi, *hYlo, *shi, *slo, *WbA, *WbB;
    float *cX, *cY, *Uh;
    cudaGetSymbolAddress((void**)&leafHi, g_leaf_hi);
    cudaGetSymbolAddress((void**)&leafLo, g_leaf_lo);
    cudaGetSymbolAddress((void**)&hXhi, g_hXhi);
    cudaGetSymbolAddress((void**)&hXlo, g_hXlo);
    cudaGetSymbolAddress((void**)&hYhi, g_hYhi);
    cudaGetSymbolAddress((void**)&hYlo, g_hYlo);
    cudaGetSymbolAddress((void**)&cX, g_cX);
    cudaGetSymbolAddress((void**)&cY, g_cY);
    cudaGetSymbolAddress((void**)&shi, g_shi);
    cudaGetSymbolAddress((void**)&slo, g_slo);
    cudaGetSymbolAddress((void**)&Uh, g_Uh);
    cudaGetSymbolAddress((void**)&WbA, g_WbA);
    cudaGetSymbolAddress((void**)&WbB, g_WbB);

    int Mp = MAXP;
    for (int lvl = 0; lvl < 13; ++lvl) {
        const bf16* chi = (lvl == 0) ? leafHi : ((lvl & 1) ? hXhi : hYhi);
        const bf16* clo = (lvl == 0) ? leafLo : ((lvl & 1) ? hXlo : hYlo);
        const float* cpv = (lvl & 1) ? cX : cY;
        bf16* dhi = (lvl & 1) ? hYhi : hXhi;
        bf16* dlo = (lvl & 1) ? hYlo : hXlo;
        float* cnx = (lvl & 1) ? cY : cX;

        { size_t t = (size_t)Mp * D_;
          hsum_split<<<(unsigned)((t + 255) / 256), 256>>>(leaf, chi, clo, lvl == 0, Mp); }

        // GEMM-B: Uh over 2*Mp children rows
        {
            dim3 g(NB / BN, (unsigned)((2 * Mp + BM - 1) / BM));
            mma_kernel<<<g, 512, DYNSM>>>(chi, clo, WbB, 2 * Mp, 0,
                                          Uh, nullptr, 1, nullptr, nullptr,
                                          nullptr, nullptr, b_iou, b_f);
        }
        // GEMM-A: gates over Mp parent rows + fused LSTM epilogue
        {
            dim3 g(NA / BN, (unsigned)((Mp + BM - 1) / BM));
            mma_kernel<<<g, 512, DYNSM>>>(shi, slo, WbA, Mp, (lvl == 12) ? 2 : 1,
                                          Uh, cpv, lvl == 0 ? 1 : 0, cnx,
                                          dhi, dlo, out, b_iou, b_f);
        }
        Mp >>= 1;
    }
}